// round 15
// baseline (speedup 1.0000x reference)
#include <cuda_runtime.h>
#include <cuda_bf16.h>
#include <math.h>

#define BB 4096
#define TT 200
#define DD 64
#define H1 80
#define H2 40
#define NEG_BIG_F (-4294967295.0f)
#define ASTRB 144
#define BSTRB 176
#define W2S 44
#define AWBYTES 4608
#define NTHR 416      // 13 warps = 13 m16 tiles

typedef unsigned long long u64;
typedef unsigned int u32;

__device__ __forceinline__ u32 smem_u32(const void* p) {
    u32 a; asm("{ .reg .u64 t; cvta.to.shared.u64 t, %1; cvt.u32.u64 %0, t; }" : "=r"(a) : "l"(p));
    return a;
}
__device__ __forceinline__ void ldmA(u32& a0, u32& a1, u32& a2, u32& a3, u32 addr) {
    asm volatile("ldmatrix.sync.aligned.m8n8.x4.shared.b16 {%0,%1,%2,%3}, [%4];"
                 : "=r"(a0), "=r"(a1), "=r"(a2), "=r"(a3) : "r"(addr));
}
__device__ __forceinline__ void ldmB(u32& b0, u32& b1, u32 addr) {
    asm volatile("ldmatrix.sync.aligned.m8n8.x2.trans.shared.b16 {%0,%1}, [%2];"
                 : "=r"(b0), "=r"(b1) : "r"(addr));
}
__device__ __forceinline__ void mma_bf16(float* d, u32 a0, u32 a1, u32 a2, u32 a3, u32 b0, u32 b1) {
    asm volatile("mma.sync.aligned.m16n8k16.row.col.f32.bf16.bf16.f32 "
                 "{%0,%1,%2,%3}, {%4,%5,%6,%7}, {%8,%9}, {%0,%1,%2,%3};"
                 : "+f"(d[0]), "+f"(d[1]), "+f"(d[2]), "+f"(d[3])
                 : "r"(a0), "r"(a1), "r"(a2), "r"(a3), "r"(b0), "r"(b1));
}
__device__ __forceinline__ unsigned short bfu(__nv_bfloat16 h) { return __bfloat16_as_ushort(h); }

__device__ __forceinline__ void split2(float x0, float x1, u32& hi, u32& lo) {
    __nv_bfloat16 h0 = __float2bfloat16_rn(x0);
    __nv_bfloat16 h1 = __float2bfloat16_rn(x1);
    __nv_bfloat16 l0 = __float2bfloat16_rn(x0 - __bfloat162float(h0));
    __nv_bfloat16 l1 = __float2bfloat16_rn(x1 - __bfloat162float(h1));
    hi = (u32)bfu(h0) | ((u32)bfu(h1) << 16);
    lo = (u32)bfu(l0) | ((u32)bfu(l1) << 16);
}

// ---------------- smem layout (float offsets) ----------------
#define OFF_AW   0            // 13 warps x 4608B (aliases c-partials, AV partials)
#define OFF_BH   14976
#define OFF_BL   17792
#define OFF_W2H  20608
#define OFF_W2L  22368
#define OFF_C    24128        // [80]
#define OFF_B2   24208        // [40]
#define OFF_WF   24248        // [40]
#define OFF_QQ   24288        // [64]
#define OFF_SC   24352        // [208]
#define OFF_RED  24560        // [16]
#define OFF_MX   24576        // [2]
#define OFF_MSK  24578        // [208] ints
#define SMEM_FLOATS 24786

__global__ __launch_bounds__(NTHR, 2)
void din_attn_kernel(const float* __restrict__ q, const float* __restrict__ kin,
                     const float* __restrict__ v, const int* __restrict__ mask,
                     const float* __restrict__ W1, const float* __restrict__ b1,
                     const float* __restrict__ W2, const float* __restrict__ b2,
                     const float* __restrict__ Wf, const float* __restrict__ bf,
                     float* __restrict__ out)
{
    extern __shared__ float sm[];
    int* msk = (int*)(sm + OFF_MSK);
    const int tid = threadIdx.x;
    const int wid = tid >> 5;
    const int lid = tid & 31;
    const int b   = blockIdx.x;
    const u32 smb = smem_u32(sm);

    if (tid < DD) sm[OFF_QQ + tid] = q[b * DD + tid];
    if (tid < 208) msk[tid] = (tid < TT) ? mask[(size_t)b * TT + tid] : 0;
    __syncthreads();

    // ---- fold W1 -> B (k x n) bf16 hi/lo ----
    {
        char* bhp = (char*)sm + (size_t)OFF_BH * 4;
        char* blp = (char*)sm + (size_t)OFF_BL * 4;
        for (int idx = tid; idx < DD * H1; idx += NTHR) {
            int i = idx / H1;
            int j = idx - i * H1;
            float w = W1[(64 + i) * H1 + j] - W1[(128 + i) * H1 + j]
                    + sm[OFF_QQ + i] * W1[(192 + i) * H1 + j];
            __nv_bfloat16 h = __float2bfloat16_rn(w);
            __nv_bfloat16 l = __float2bfloat16_rn(w - __bfloat162float(h));
            size_t o = (size_t)i * BSTRB + (size_t)j * 2;
            *(unsigned short*)(bhp + o) = bfu(h);
            *(unsigned short*)(blp + o) = bfu(l);
        }
    }

    // ---- W2^T bf16 hi/lo ----
    {
        char* w2h = (char*)sm + (size_t)OFF_W2H * 4;
        char* w2l = (char*)sm + (size_t)OFF_W2L * 4;
        for (int idx = tid; idx < H1 * H2; idx += NTHR) {
            int j = idx / H2;
            int g = idx - j * H2;
            float w = W2[idx];
            __nv_bfloat16 h = __float2bfloat16_rn(w);
            __nv_bfloat16 l = __float2bfloat16_rn(w - __bfloat162float(h));
            size_t o = (size_t)g * (W2S * 4) + (size_t)j * 2;
            *(unsigned short*)(w2h + o) = bfu(h);
            *(unsigned short*)(w2l + o) = bfu(l);
        }
    }
    if (tid < H2) { sm[OFF_B2 + tid] = b2[tid]; sm[OFF_WF + tid] = Wf[tid]; }

    // ---- bias c: 3-way i-split over 240 threads (partials alias AW region) ----
    if (tid < 240) {
        const int blk = tid / 80;
        const int jj  = tid - blk * 80;
        const int i0  = blk * 21;
        const int i1  = (blk == 2) ? 64 : i0 + 21;
        float acc = (blk == 0) ? b1[jj] : 0.0f;
        for (int i = i0; i < i1; i++)
            acc += sm[OFF_QQ + i] * (W1[i * H1 + jj] + W1[(128 + i) * H1 + jj]);
        sm[OFF_AW + tid] = acc;
    }
    __syncthreads();
    if (tid < H1)
        sm[OFF_C + tid] = sm[OFF_AW + tid] + sm[OFF_AW + tid + 80] + sm[OFF_AW + tid + 160];
    __syncthreads();

    // ---- fused: per-warp A convert -> GEMM1 -> relu -> GEMM2 -> scores ----
    {
        const int m0 = wid * 16;

        // per-warp convert of this tile's 16 rows (unconditional, fully coalesced)
        {
            char* aw = (char*)sm + (size_t)wid * AWBYTES;
            #pragma unroll
            for (int r = 0; r < 8; r++) {
                int idx = lid + r * 32;
                int t  = idx >> 4;
                int ch = idx & 15;
                int row = m0 + t;
                uint2 hv = make_uint2(0u, 0u), lv = make_uint2(0u, 0u);
                if (row < TT) {
                    float4 kv = *(const float4*)(kin + ((size_t)b * TT + row) * DD + ch * 4);
                    u32 h0, l0, h1, l1;
                    split2(kv.x, kv.y, h0, l0);
                    split2(kv.z, kv.w, h1, l1);
                    hv = make_uint2(h0, h1);
                    lv = make_uint2(l0, l1);
                }
                size_t o = (size_t)t * ASTRB + (size_t)ch * 8;
                *(uint2*)(aw + o) = hv;
                *(uint2*)(aw + 2304 + o) = lv;
            }
            __syncwarp();
        }

        // L2 prefetch of this tile's unmasked V rows (overlaps with MMA below)
        {
            const int row = m0 + (lid >> 1);
            const int half = lid & 1;
            if (row < TT && msk[row] != 0) {
                const float* vp = v + (size_t)b * TT * DD + (size_t)row * DD + half * 32;
                asm volatile("prefetch.global.L2 [%0];" :: "l"(vp));
            }
        }

        const u32 aRowH = smb + wid * AWBYTES + (lid & 15) * ASTRB + (lid >> 4) * 16;
        const u32 aRowL = aRowH + 2304;
        const u32 bRowH = smb + OFF_BH * 4 + (lid & 15) * BSTRB;
        const u32 bRowL = smb + OFF_BL * 4 + (lid & 15) * BSTRB;

        float acc[10][4];
        #pragma unroll
        for (int n = 0; n < 10; n++) {
            acc[n][0] = 0.f; acc[n][1] = 0.f; acc[n][2] = 0.f; acc[n][3] = 0.f;
        }
        #pragma unroll
        for (int k = 0; k < 4; k++) {
            u32 ah0, ah1, ah2, ah3, al0, al1, al2, al3;
            ldmA(ah0, ah1, ah2, ah3, aRowH + k * 32);
            ldmA(al0, al1, al2, al3, aRowL + k * 32);
            #pragma unroll
            for (int n = 0; n < 10; n++) {
                u32 bh0, bh1, bl0, bl1;
                ldmB(bh0, bh1, bRowH + k * 16 * BSTRB + n * 16);
                ldmB(bl0, bl1, bRowL + k * 16 * BSTRB + n * 16);
                mma_bf16(acc[n], ah0, ah1, ah2, ah3, bh0, bh1);
                mma_bf16(acc[n], al0, al1, al2, al3, bh0, bh1);
                mma_bf16(acc[n], ah0, ah1, ah2, ah3, bl0, bl1);
            }
        }

        // bias + relu, in-register split to GEMM2 A-frags
        u32 fh[5][4], fl[5][4];
        {
            const int cc = (lid & 3) * 2;
            #pragma unroll
            for (int n = 0; n < 10; n++) {
                const float c0 = sm[OFF_C + n * 8 + cc];
                const float c1 = sm[OFF_C + n * 8 + cc + 1];
                float x0 = fmaxf(acc[n][0] + c0, 0.f);
                float x1 = fmaxf(acc[n][1] + c1, 0.f);
                float x2 = fmaxf(acc[n][2] + c0, 0.f);
                float x3 = fmaxf(acc[n][3] + c1, 0.f);
                const int kk = n >> 1;
                const int hi2 = (n & 1) * 2;
                split2(x0, x1, fh[kk][hi2],     fl[kk][hi2]);
                split2(x2, x3, fh[kk][hi2 + 1], fl[kk][hi2 + 1]);
            }
        }

        // GEMM2
        float acc2[5][4];
        {
            const int cc = (lid & 3) * 2;
            #pragma unroll
            for (int n2 = 0; n2 < 5; n2++) {
                const float bb0 = sm[OFF_B2 + n2 * 8 + cc];
                const float bb1 = sm[OFF_B2 + n2 * 8 + cc + 1];
                acc2[n2][0] = bb0; acc2[n2][1] = bb1;
                acc2[n2][2] = bb0; acc2[n2][3] = bb1;
            }
        }
        {
            const int nrow = (lid >> 2);
            const int kw   = (lid & 3);
            #pragma unroll
            for (int kk = 0; kk < 5; kk++) {
                #pragma unroll
                for (int n2 = 0; n2 < 5; n2++) {
                    const u32 base = (u32)(((n2 * 8 + nrow) * W2S + kk * 8 + kw) * 4);
                    u32 bh0 = *(const u32*)((char*)sm + (size_t)OFF_W2H * 4 + base);
                    u32 bh1 = *(const u32*)((char*)sm + (size_t)OFF_W2H * 4 + base + 16);
                    u32 bl0 = *(const u32*)((char*)sm + (size_t)OFF_W2L * 4 + base);
                    u32 bl1 = *(const u32*)((char*)sm + (size_t)OFF_W2L * 4 + base + 16);
                    mma_bf16(acc2[n2], fh[kk][0], fh[kk][1], fh[kk][2], fh[kk][3], bh0, bh1);
                    mma_bf16(acc2[n2], fl[kk][0], fl[kk][1], fl[kk][2], fl[kk][3], bh0, bh1);
                    mma_bf16(acc2[n2], fh[kk][0], fh[kk][1], fh[kk][2], fh[kk][3], bl0, bl1);
                }
            }
        }

        // scores: relu(acc2) . Wf, quad reduce
        {
            const int cc = (lid & 3) * 2;
            float s0 = 0.f, s1 = 0.f;
            #pragma unroll
            for (int n2 = 0; n2 < 5; n2++) {
                const float w0 = sm[OFF_WF + n2 * 8 + cc];
                const float w1 = sm[OFF_WF + n2 * 8 + cc + 1];
                s0 = fmaf(fmaxf(acc2[n2][0], 0.f), w0, s0);
                s0 = fmaf(fmaxf(acc2[n2][1], 0.f), w1, s0);
                s1 = fmaf(fmaxf(acc2[n2][2], 0.f), w0, s1);
                s1 = fmaf(fmaxf(acc2[n2][3], 0.f), w1, s1);
            }
            s0 += __shfl_xor_sync(0xffffffffu, s0, 1);
            s0 += __shfl_xor_sync(0xffffffffu, s0, 2);
            s1 += __shfl_xor_sync(0xffffffffu, s1, 1);
            s1 += __shfl_xor_sync(0xffffffffu, s1, 2);
            if ((lid & 3) == 0) {
                const int r0 = m0 + (lid >> 2);
                if (r0 < TT)     sm[OFF_SC + r0] = s0;
                if (r0 + 8 < TT) sm[OFF_SC + r0 + 8] = s1;
            }
        }
    }
    __syncthreads();

    // ---- bias + mask ----
    if (tid < TT) {
        float s = sm[OFF_SC + tid] + bf[0];
        if (msk[tid] == 0) s = NEG_BIG_F;
        sm[OFF_SC + tid] = s;
    }
    __syncthreads();

    // ---- softmax over T ----
    float mval = (tid < TT) ? sm[OFF_SC + tid] : -3.0e38f;
    #pragma unroll
    for (int o = 16; o; o >>= 1)
        mval = fmaxf(mval, __shfl_xor_sync(0xffffffffu, mval, o));
    if (lid == 0) sm[OFF_RED + wid] = mval;
    __syncthreads();
    if (tid == 0) {
        float m = sm[OFF_RED];
        #pragma unroll
        for (int w = 1; w < 13; w++) m = fmaxf(m, sm[OFF_RED + w]);
        sm[OFF_MX] = m;
    }
    __syncthreads();
    const float mx = sm[OFF_MX];
    float e = (tid < TT) ? __expf(sm[OFF_SC + tid] - mx) : 0.0f;
    if (tid < TT) sm[OFF_SC + tid] = e;
    float sval = e;
    #pragma unroll
    for (int o = 16; o; o >>= 1)
        sval += __shfl_xor_sync(0xffffffffu, sval, o);
    if (lid == 0) sm[OFF_RED + wid] = sval;
    __syncthreads();
    if (tid == 0) {
        float smv = 0.0f;
        #pragma unroll
        for (int w = 0; w < 13; w++) smv += sm[OFF_RED + w];
        sm[OFF_MX + 1] = 1.0f / smv;
    }
    __syncthreads();

    // ---- out = attn @ V ; group-uniform skip of zero-weight rows ----
    const float inv = sm[OFF_MX + 1];
    if (tid < 384) {
        const int g  = tid >> 6;
        const int dd = tid & 63;
        const int start = g * 33 + (g < 2 ? g : 2);
        const int cnt   = (g < 2) ? 34 : 33;
        const float* vb = v + (size_t)b * TT * DD;
        const float* scp = sm + OFF_SC;
        float a0 = 0.f, a1 = 0.f;
        for (int t = start; t < start + cnt; t++) {
            const float w = scp[t];
            if (w != 0.0f) {    // uniform across the 64-thread group
                if (t & 1) a1 = fmaf(w, vb[(size_t)t * DD + dd], a1);
                else       a0 = fmaf(w, vb[(size_t)t * DD + dd], a0);
            }
        }
        sm[OFF_AW + tid] = a0 + a1;
    }
    __syncthreads();
    if (tid < DD) {
        float r = 0.f;
        #pragma unroll
        for (int g = 0; g < 6; g++) r += sm[OFF_AW + tid + 64 * g];
        out[(size_t)b * DD + tid] = r * inv;
    }
}

extern "C" void kernel_launch(void* const* d_in, const int* in_sizes, int n_in,
                              void* d_out, int out_size)
{
    const float* q    = (const float*)d_in[0];
    const float* k    = (const float*)d_in[1];
    const float* v    = (const float*)d_in[2];
    const int*   mask = (const int*)  d_in[3];
    const float* W1   = (const float*)d_in[4];
    const float* b1   = (const float*)d_in[5];
    const float* W2   = (const float*)d_in[6];
    const float* b2   = (const float*)d_in[7];
    const float* Wf   = (const float*)d_in[8];
    const float* bf   = (const float*)d_in[9];
    float* out = (float*)d_out;

    const int smem_bytes = SMEM_FLOATS * (int)sizeof(float);
    cudaFuncSetAttribute(din_attn_kernel,
                         cudaFuncAttributeMaxDynamicSharedMemorySize, smem_bytes);
    din_attn_kernel<<<BB, NTHR, smem_bytes>>>(q, k, v, mask, W1, b1, W2, b2, Wf, bf, out);
}

// round 16
// speedup vs baseline: 1.2568x; 1.2568x over previous
#include <cuda_runtime.h>
#include <cuda_bf16.h>
#include <math.h>

#define BB 4096
#define TT 200
#define DD 64
#define H1 80
#define H2 40
#define NEG_BIG_F (-4294967295.0f)
#define ASTRB 144
#define BSTRB 176
#define W2S 44
#define AWBYTES 4608
#define NTHR 416      // 13 warps = 13 m16 tiles

typedef unsigned long long u64;
typedef unsigned int u32;

__device__ __forceinline__ u32 smem_u32(const void* p) {
    u32 a; asm("{ .reg .u64 t; cvta.to.shared.u64 t, %1; cvt.u32.u64 %0, t; }" : "=r"(a) : "l"(p));
    return a;
}
__device__ __forceinline__ void ldmA(u32& a0, u32& a1, u32& a2, u32& a3, u32 addr) {
    asm volatile("ldmatrix.sync.aligned.m8n8.x4.shared.b16 {%0,%1,%2,%3}, [%4];"
                 : "=r"(a0), "=r"(a1), "=r"(a2), "=r"(a3) : "r"(addr));
}
__device__ __forceinline__ void ldmB(u32& b0, u32& b1, u32 addr) {
    asm volatile("ldmatrix.sync.aligned.m8n8.x2.trans.shared.b16 {%0,%1}, [%2];"
                 : "=r"(b0), "=r"(b1) : "r"(addr));
}
__device__ __forceinline__ void mma_bf16(float* d, u32 a0, u32 a1, u32 a2, u32 a3, u32 b0, u32 b1) {
    asm volatile("mma.sync.aligned.m16n8k16.row.col.f32.bf16.bf16.f32 "
                 "{%0,%1,%2,%3}, {%4,%5,%6,%7}, {%8,%9}, {%0,%1,%2,%3};"
                 : "+f"(d[0]), "+f"(d[1]), "+f"(d[2]), "+f"(d[3])
                 : "r"(a0), "r"(a1), "r"(a2), "r"(a3), "r"(b0), "r"(b1));
}
__device__ __forceinline__ unsigned short bfu(__nv_bfloat16 h) { return __bfloat16_as_ushort(h); }

__device__ __forceinline__ void split2(float x0, float x1, u32& hi, u32& lo) {
    __nv_bfloat16 h0 = __float2bfloat16_rn(x0);
    __nv_bfloat16 h1 = __float2bfloat16_rn(x1);
    __nv_bfloat16 l0 = __float2bfloat16_rn(x0 - __bfloat162float(h0));
    __nv_bfloat16 l1 = __float2bfloat16_rn(x1 - __bfloat162float(h1));
    hi = (u32)bfu(h0) | ((u32)bfu(h1) << 16);
    lo = (u32)bfu(l0) | ((u32)bfu(l1) << 16);
}

// ---------------- smem layout (float offsets) ----------------
#define OFF_AW   0            // 13 warps x 4608B (aliases c-partials, AV partials)
#define OFF_BH   14976
#define OFF_BL   17792
#define OFF_W2H  20608
#define OFF_W2L  22368
#define OFF_C    24128        // [80]
#define OFF_B2   24208        // [40]
#define OFF_WF   24248        // [40]
#define OFF_QQ   24288        // [64]
#define OFF_SC   24352        // [208]
#define OFF_RED  24560        // [16]
#define OFF_MX   24576        // [2]
#define SMEM_FLOATS 24578

__global__ __launch_bounds__(NTHR, 2)
void din_attn_kernel(const float* __restrict__ q, const float* __restrict__ kin,
                     const float* __restrict__ v, const int* __restrict__ mask,
                     const float* __restrict__ W1, const float* __restrict__ b1,
                     const float* __restrict__ W2, const float* __restrict__ b2,
                     const float* __restrict__ Wf, const float* __restrict__ bf,
                     float* __restrict__ out)
{
    extern __shared__ float sm[];
    const int tid = threadIdx.x;
    const int wid = tid >> 5;
    const int lid = tid & 31;
    const int b   = blockIdx.x;
    const u32 smb = smem_u32(sm);

    if (tid < DD) sm[OFF_QQ + tid] = q[b * DD + tid];
    __syncthreads();

    // ---- fold W1 -> B (k x n) bf16 hi/lo ----
    {
        char* bhp = (char*)sm + (size_t)OFF_BH * 4;
        char* blp = (char*)sm + (size_t)OFF_BL * 4;
        for (int idx = tid; idx < DD * H1; idx += NTHR) {
            int i = idx / H1;
            int j = idx - i * H1;
            float w = W1[(64 + i) * H1 + j] - W1[(128 + i) * H1 + j]
                    + sm[OFF_QQ + i] * W1[(192 + i) * H1 + j];
            __nv_bfloat16 h = __float2bfloat16_rn(w);
            __nv_bfloat16 l = __float2bfloat16_rn(w - __bfloat162float(h));
            size_t o = (size_t)i * BSTRB + (size_t)j * 2;
            *(unsigned short*)(bhp + o) = bfu(h);
            *(unsigned short*)(blp + o) = bfu(l);
        }
    }

    // ---- W2^T bf16 hi/lo ----
    {
        char* w2h = (char*)sm + (size_t)OFF_W2H * 4;
        char* w2l = (char*)sm + (size_t)OFF_W2L * 4;
        for (int idx = tid; idx < H1 * H2; idx += NTHR) {
            int j = idx / H2;
            int g = idx - j * H2;
            float w = W2[idx];
            __nv_bfloat16 h = __float2bfloat16_rn(w);
            __nv_bfloat16 l = __float2bfloat16_rn(w - __bfloat162float(h));
            size_t o = (size_t)g * (W2S * 4) + (size_t)j * 2;
            *(unsigned short*)(w2h + o) = bfu(h);
            *(unsigned short*)(w2l + o) = bfu(l);
        }
    }
    if (tid < H2) { sm[OFF_B2 + tid] = b2[tid]; sm[OFF_WF + tid] = Wf[tid]; }

    // ---- bias c: 3-way i-split over 240 threads (partials alias AW region) ----
    if (tid < 240) {
        const int blk = tid / 80;
        const int jj  = tid - blk * 80;
        const int i0  = blk * 21;
        const int i1  = (blk == 2) ? 64 : i0 + 21;
        float acc = (blk == 0) ? b1[jj] : 0.0f;
        for (int i = i0; i < i1; i++)
            acc += sm[OFF_QQ + i] * (W1[i * H1 + jj] + W1[(128 + i) * H1 + jj]);
        sm[OFF_AW + tid] = acc;
    }
    __syncthreads();
    if (tid < H1)
        sm[OFF_C + tid] = sm[OFF_AW + tid] + sm[OFF_AW + tid + 80] + sm[OFF_AW + tid + 160];
    __syncthreads();

    // ---- fused: per-warp A convert -> GEMM1 -> relu -> GEMM2 -> scores ----
    {
        const int m0 = wid * 16;

        // per-warp convert: batch all 8 LDG.128 first (MLP=8), then convert+store
        {
            char* aw = (char*)sm + (size_t)wid * AWBYTES;
            float4 kvr[8];
            #pragma unroll
            for (int r = 0; r < 8; r++) {
                int idx = lid + r * 32;
                int t  = idx >> 4;
                int ch = idx & 15;
                int row = m0 + t;
                kvr[r] = (row < TT)
                    ? *(const float4*)(kin + ((size_t)b * TT + row) * DD + ch * 4)
                    : make_float4(0.f, 0.f, 0.f, 0.f);
            }
            #pragma unroll
            for (int r = 0; r < 8; r++) {
                int idx = lid + r * 32;
                int t  = idx >> 4;
                int ch = idx & 15;
                u32 h0, l0, h1, l1;
                split2(kvr[r].x, kvr[r].y, h0, l0);
                split2(kvr[r].z, kvr[r].w, h1, l1);
                size_t o = (size_t)t * ASTRB + (size_t)ch * 8;
                *(uint2*)(aw + o)        = make_uint2(h0, h1);
                *(uint2*)(aw + 2304 + o) = make_uint2(l0, l1);
            }
            __syncwarp();
        }

        const u32 aRowH = smb + wid * AWBYTES + (lid & 15) * ASTRB + (lid >> 4) * 16;
        const u32 aRowL = aRowH + 2304;
        const u32 bRowH = smb + OFF_BH * 4 + (lid & 15) * BSTRB;
        const u32 bRowL = smb + OFF_BL * 4 + (lid & 15) * BSTRB;

        float acc[10][4];
        #pragma unroll
        for (int n = 0; n < 10; n++) {
            acc[n][0] = 0.f; acc[n][1] = 0.f; acc[n][2] = 0.f; acc[n][3] = 0.f;
        }
        #pragma unroll
        for (int k = 0; k < 4; k++) {
            u32 ah0, ah1, ah2, ah3, al0, al1, al2, al3;
            ldmA(ah0, ah1, ah2, ah3, aRowH + k * 32);
            ldmA(al0, al1, al2, al3, aRowL + k * 32);
            #pragma unroll
            for (int n = 0; n < 10; n++) {
                u32 bh0, bh1, bl0, bl1;
                ldmB(bh0, bh1, bRowH + k * 16 * BSTRB + n * 16);
                ldmB(bl0, bl1, bRowL + k * 16 * BSTRB + n * 16);
                mma_bf16(acc[n], ah0, ah1, ah2, ah3, bh0, bh1);
                mma_bf16(acc[n], al0, al1, al2, al3, bh0, bh1);
                mma_bf16(acc[n], ah0, ah1, ah2, ah3, bl0, bl1);
            }
        }

        // bias + relu, in-register split to GEMM2 A-frags
        u32 fh[5][4], fl[5][4];
        {
            const int cc = (lid & 3) * 2;
            #pragma unroll
            for (int n = 0; n < 10; n++) {
                const float c0 = sm[OFF_C + n * 8 + cc];
                const float c1 = sm[OFF_C + n * 8 + cc + 1];
                float x0 = fmaxf(acc[n][0] + c0, 0.f);
                float x1 = fmaxf(acc[n][1] + c1, 0.f);
                float x2 = fmaxf(acc[n][2] + c0, 0.f);
                float x3 = fmaxf(acc[n][3] + c1, 0.f);
                const int kk = n >> 1;
                const int hi2 = (n & 1) * 2;
                split2(x0, x1, fh[kk][hi2],     fl[kk][hi2]);
                split2(x2, x3, fh[kk][hi2 + 1], fl[kk][hi2 + 1]);
            }
        }

        // GEMM2
        float acc2[5][4];
        {
            const int cc = (lid & 3) * 2;
            #pragma unroll
            for (int n2 = 0; n2 < 5; n2++) {
                const float bb0 = sm[OFF_B2 + n2 * 8 + cc];
                const float bb1 = sm[OFF_B2 + n2 * 8 + cc + 1];
                acc2[n2][0] = bb0; acc2[n2][1] = bb1;
                acc2[n2][2] = bb0; acc2[n2][3] = bb1;
            }
        }
        {
            const int nrow = (lid >> 2);
            const int kw   = (lid & 3);
            #pragma unroll
            for (int kk = 0; kk < 5; kk++) {
                #pragma unroll
                for (int n2 = 0; n2 < 5; n2++) {
                    const u32 base = (u32)(((n2 * 8 + nrow) * W2S + kk * 8 + kw) * 4);
                    u32 bh0 = *(const u32*)((char*)sm + (size_t)OFF_W2H * 4 + base);
                    u32 bh1 = *(const u32*)((char*)sm + (size_t)OFF_W2H * 4 + base + 16);
                    u32 bl0 = *(const u32*)((char*)sm + (size_t)OFF_W2L * 4 + base);
                    u32 bl1 = *(const u32*)((char*)sm + (size_t)OFF_W2L * 4 + base + 16);
                    mma_bf16(acc2[n2], fh[kk][0], fh[kk][1], fh[kk][2], fh[kk][3], bh0, bh1);
                    mma_bf16(acc2[n2], fl[kk][0], fl[kk][1], fl[kk][2], fl[kk][3], bh0, bh1);
                    mma_bf16(acc2[n2], fh[kk][0], fh[kk][1], fh[kk][2], fh[kk][3], bl0, bl1);
                }
            }
        }

        // scores: relu(acc2) . Wf, quad reduce
        {
            const int cc = (lid & 3) * 2;
            float s0 = 0.f, s1 = 0.f;
            #pragma unroll
            for (int n2 = 0; n2 < 5; n2++) {
                const float w0 = sm[OFF_WF + n2 * 8 + cc];
                const float w1 = sm[OFF_WF + n2 * 8 + cc + 1];
                s0 = fmaf(fmaxf(acc2[n2][0], 0.f), w0, s0);
                s0 = fmaf(fmaxf(acc2[n2][1], 0.f), w1, s0);
                s1 = fmaf(fmaxf(acc2[n2][2], 0.f), w0, s1);
                s1 = fmaf(fmaxf(acc2[n2][3], 0.f), w1, s1);
            }
            s0 += __shfl_xor_sync(0xffffffffu, s0, 1);
            s0 += __shfl_xor_sync(0xffffffffu, s0, 2);
            s1 += __shfl_xor_sync(0xffffffffu, s1, 1);
            s1 += __shfl_xor_sync(0xffffffffu, s1, 2);
            if ((lid & 3) == 0) {
                const int r0 = m0 + (lid >> 2);
                if (r0 < TT)     sm[OFF_SC + r0] = s0;
                if (r0 + 8 < TT) sm[OFF_SC + r0 + 8] = s1;
            }
        }
    }
    __syncthreads();

    // ---- bias + mask ----
    if (tid < TT) {
        float s = sm[OFF_SC + tid] + bf[0];
        if (mask[(size_t)b * TT + tid] == 0) s = NEG_BIG_F;
        sm[OFF_SC + tid] = s;
    }
    __syncthreads();

    // ---- softmax over T (13 warps) ----
    float mval = (tid < TT) ? sm[OFF_SC + tid] : -3.0e38f;
    #pragma unroll
    for (int o = 16; o; o >>= 1)
        mval = fmaxf(mval, __shfl_xor_sync(0xffffffffu, mval, o));
    if (lid == 0) sm[OFF_RED + wid] = mval;
    __syncthreads();
    if (tid == 0) {
        float m = sm[OFF_RED];
        #pragma unroll
        for (int w = 1; w < 13; w++) m = fmaxf(m, sm[OFF_RED + w]);
        sm[OFF_MX] = m;
    }
    __syncthreads();
    const float mx = sm[OFF_MX];
    float e = (tid < TT) ? __expf(sm[OFF_SC + tid] - mx) : 0.0f;
    if (tid < TT) sm[OFF_SC + tid] = e;
    float sval = e;
    #pragma unroll
    for (int o = 16; o; o >>= 1)
        sval += __shfl_xor_sync(0xffffffffu, sval, o);
    if (lid == 0) sm[OFF_RED + wid] = sval;
    __syncthreads();
    if (tid == 0) {
        float smv = 0.0f;
        #pragma unroll
        for (int w = 0; w < 13; w++) smv += sm[OFF_RED + w];
        sm[OFF_MX + 1] = 1.0f / smv;
    }
    __syncthreads();

    // ---- out = attn @ V : chunks of 8 batched loads (MLP=8), 4 acc chains ----
    const float inv = sm[OFF_MX + 1];
    if (tid < 384) {
        const int g  = tid >> 6;
        const int dd = tid & 63;
        const int start = g * 33 + (g < 2 ? g : 2);
        const int cnt   = (g < 2) ? 34 : 33;
        const float* vb = v + (size_t)b * TT * DD + dd;
        const float* scp = sm + OFF_SC;
        float a0 = 0.f, a1 = 0.f, a2 = 0.f, a3 = 0.f;
        int t = start;
        const int tend = start + cnt;
        for (; t + 8 <= tend; t += 8) {
            float vv[8];
            #pragma unroll
            for (int u = 0; u < 8; u++) vv[u] = vb[(size_t)(t + u) * DD];
            a0 = fmaf(scp[t + 0], vv[0], a0);
            a1 = fmaf(scp[t + 1], vv[1], a1);
            a2 = fmaf(scp[t + 2], vv[2], a2);
            a3 = fmaf(scp[t + 3], vv[3], a3);
            a0 = fmaf(scp[t + 4], vv[4], a0);
            a1 = fmaf(scp[t + 5], vv[5], a1);
            a2 = fmaf(scp[t + 6], vv[6], a2);
            a3 = fmaf(scp[t + 7], vv[7], a3);
        }
        for (; t < tend; t++)
            a0 = fmaf(scp[t], vb[(size_t)t * DD], a0);
        sm[OFF_AW + tid] = (a0 + a1) + (a2 + a3);
    }
    __syncthreads();
    if (tid < DD) {
        float r = 0.f;
        #pragma unroll
        for (int g = 0; g < 6; g++) r += sm[OFF_AW + tid + 64 * g];
        out[(size_t)b * DD + tid] = r * inv;
    }
}

extern "C" void kernel_launch(void* const* d_in, const int* in_sizes, int n_in,
                              void* d_out, int out_size)
{
    const float* q    = (const float*)d_in[0];
    const float* k    = (const float*)d_in[1];
    const float* v    = (const float*)d_in[2];
    const int*   mask = (const int*)  d_in[3];
    const float* W1   = (const float*)d_in[4];
    const float* b1   = (const float*)d_in[5];
    const float* W2   = (const float*)d_in[6];
    const float* b2   = (const float*)d_in[7];
    const float* Wf   = (const float*)d_in[8];
    const float* bf   = (const float*)d_in[9];
    float* out = (float*)d_out;

    const int smem_bytes = SMEM_FLOATS * (int)sizeof(float);
    cudaFuncSetAttribute(din_attn_kernel,
                         cudaFuncAttributeMaxDynamicSharedMemorySize, smem_bytes);
    din_attn_kernel<<<BB, NTHR, smem_bytes>>>(q, k, v, mask, W1, b1, W2, b2, Wf, bf, out);
}